// round 2
// baseline (speedup 1.0000x reference)
#include <cuda_runtime.h>
#include <cuda_fp16.h>
#include <cstdint>

// ============================================================================
// LaminiIndex: full attention over 65536 embeddings.
//   logits = Q(4096x128) K^T ; P = softmax(logits) ; out_k = P K ; out_v = P V
// Strategy: tcgen05 fp16 flash attention, split-precision QK (hi/lo fp16,
// 3 MMAs -> ~fp32-exact logits), fixed-max 2-pass softmax (no TMEM rescale),
// split-KV x4 + reduction kernel.
// tcgen05 is arch-ACCELERATED: only legal under sm_103a/sm_100a targets, so
// the device body is guarded by the family feature macros; the plain
// compute_103 PTX pass compiles a stub (never selected at runtime on GB300).
// ============================================================================

#if defined(__CUDA_ARCH_FEAT_SM103_ALL) || defined(__CUDA_ARCH_FEAT_SM100_ALL)
#define HX_HAS_TCGEN05 1
#else
#define HX_HAS_TCGEN05 0
#endif

#define D        128
#define NQ       4096
#define NKEYS    65536
#define NSPLIT   4
#define KEYS_PER_SPLIT (NKEYS / NSPLIT)   // 16384
#define BN       128
#define NTILES   (KEYS_PER_SPLIT / BN)    // 128
#define NQTILES  (NQ / 128)               // 32
#define NCTA     (NSPLIT * NQTILES)       // 128

// ---------------- device scratch (allowed: __device__ globals) -------------
__device__ __half g_qhi[NQ * D];
__device__ __half g_qlo[NQ * D];
__device__ __half g_khi[(size_t)NKEYS * D];
__device__ __half g_klo[(size_t)NKEYS * D];
__device__ __half g_kthi[(size_t)D * NKEYS];   // transposed keys  [d][n]
__device__ __half g_vthi[(size_t)D * NKEYS];   // transposed values [d][n]
__device__ float  g_ok[(size_t)NSPLIT * NQ * D];
__device__ float  g_ov[(size_t)NSPLIT * NQ * D];
__device__ float  g_m[NSPLIT * NQ];
__device__ float  g_l[NSPLIT * NQ];

// ---------------- PTX helpers ----------------------------------------------
__device__ __forceinline__ uint32_t hx_smem_u32(const void* p) {
    uint32_t a;
    asm("{ .reg .u64 t; cvta.to.shared.u64 t, %1; cvt.u32.u64 %0, t; }"
        : "=r"(a) : "l"(p));
    return a;
}
__device__ __forceinline__ uint32_t hx_elect() {
    uint32_t p;
    asm volatile("{\n\t.reg .pred p;\n\telect.sync _|p, 0xFFFFFFFF;\n\t"
                 "selp.b32 %0, 1, 0, p;\n\t}" : "=r"(p));
    return p;
}
#define HX_TCALLOC(sa, n) \
    asm volatile("tcgen05.alloc.cta_group::1.sync.aligned.shared::cta.b32 [%0], %1;" \
                 :: "r"((uint32_t)(sa)), "r"((uint32_t)(n)) : "memory")
#define HX_TCDEALLOC(t, n) \
    asm volatile("tcgen05.dealloc.cta_group::1.sync.aligned.b32 %0, %1;" :: "r"(t), "r"(n))
#define HX_TCRELINQ() \
    asm volatile("tcgen05.relinquish_alloc_permit.cta_group::1.sync.aligned;")
#define HX_COMMIT(mb) \
    asm volatile("tcgen05.commit.cta_group::1.mbarrier::arrive::one.shared::cluster.b64 [%0];" \
                 :: "r"((uint32_t)(mb)) : "memory")
#define HX_FENCE_BEFORE() asm volatile("tcgen05.fence::before_thread_sync;" ::: "memory")
#define HX_FENCE_AFTER()  asm volatile("tcgen05.fence::after_thread_sync;" ::: "memory")
#define HX_WAIT_LD()      asm volatile("tcgen05.wait::ld.sync.aligned;" ::: "memory")
#define HX_FENCE_ASYNC()  asm volatile("fence.proxy.async.shared::cta;" ::: "memory")
#define HX_MBINIT(mb, c) \
    asm volatile("mbarrier.init.shared.b64 [%0], %1;" \
                 :: "r"((uint32_t)(mb)), "r"((uint32_t)(c)) : "memory")

#define HX_MBWAIT(mbaddr, ph) do {                                            \
    uint32_t _mb = (uint32_t)(mbaddr);                                        \
    uint32_t _pa = (uint32_t)(ph);                                            \
    uint32_t _done;                                                           \
    asm volatile("{\n\t.reg .pred p;\n\t"                                     \
        "mbarrier.try_wait.parity.acquire.cta.shared::cta.b64 p, [%1], %2;\n\t" \
        "selp.b32 %0, 1, 0, p;\n\t}"                                          \
        : "=r"(_done) : "r"(_mb), "r"(_pa) : "memory");                       \
    if (!_done) {                                                             \
        asm volatile("{\n\t.reg .pred P1;\n\t"                                \
            "WL_%=:\n\t"                                                      \
            "mbarrier.try_wait.parity.acquire.cta.shared::cta.b64 P1, [%0], %1, 0x989680;\n\t" \
            "@P1 bra.uni WD_%=;\n\t"                                          \
            "bra.uni WL_%=;\n\t"                                              \
            "WD_%=:\n\t}" :: "r"(_mb), "r"(_pa) : "memory");                  \
    }                                                                         \
} while (0)

#define HX_LDTM_X32(r, addr) \
    asm volatile("tcgen05.ld.sync.aligned.32x32b.x32.b32 "                    \
        "{%0, %1, %2, %3, %4, %5, %6, %7, %8, %9, %10, %11, %12, %13, %14, %15, " \
        " %16, %17, %18, %19, %20, %21, %22, %23, %24, %25, %26, %27, %28, %29, %30, %31}, [%32];" \
        : "=r"((r)[0]),  "=r"((r)[1]),  "=r"((r)[2]),  "=r"((r)[3]),          \
          "=r"((r)[4]),  "=r"((r)[5]),  "=r"((r)[6]),  "=r"((r)[7]),          \
          "=r"((r)[8]),  "=r"((r)[9]),  "=r"((r)[10]), "=r"((r)[11]),         \
          "=r"((r)[12]), "=r"((r)[13]), "=r"((r)[14]), "=r"((r)[15]),         \
          "=r"((r)[16]), "=r"((r)[17]), "=r"((r)[18]), "=r"((r)[19]),         \
          "=r"((r)[20]), "=r"((r)[21]), "=r"((r)[22]), "=r"((r)[23]),         \
          "=r"((r)[24]), "=r"((r)[25]), "=r"((r)[26]), "=r"((r)[27]),         \
          "=r"((r)[28]), "=r"((r)[29]), "=r"((r)[30]), "=r"((r)[31])          \
        : "r"(addr))

__device__ __forceinline__ void hx_mma_f16_ss(uint32_t d, uint64_t a, uint64_t b,
                                              uint32_t idesc, uint32_t acc) {
#if HX_HAS_TCGEN05
    asm volatile("{\n\t.reg .pred p;\n\tsetp.ne.u32 p, %5, 0;\n\t"
        "tcgen05.mma.cta_group::1.kind::f16 [%0], %1, %2, %3, {%4, %4, %4, %4}, p;\n\t}"
        :: "r"(d), "l"(a), "l"(b), "r"(idesc), "r"(0u), "r"(acc) : "memory");
#endif
}

// SW128 K-major SMEM descriptor (LBO=1, SBO=64, version=1) — test_mma_iter layout.
__device__ __forceinline__ uint64_t hx_desc(uint32_t saddr) {
    return ((uint64_t)2 << 61) | ((uint64_t)1 << 46) | ((uint64_t)64 << 32) |
           ((uint64_t)1 << 16) | ((uint64_t)(saddr >> 4) & 0x3FFF);
}

// idesc kind::f16: dtype=F32(1<<4), atype=btype=F16(0), N=128 (16<<17), M=128 (8<<24)
#define HX_IDESC 0x08200010u

// K-step descriptor offset (16 fp16 = 32B per step; 128-row tile => 16 atom rows,
// atom-col 1 starts at 16*1024 B = 1024 units of 16B).
__device__ __forceinline__ uint64_t hx_koff(int kk) {
    return (kk < 4) ? (uint64_t)(kk * 2) : (uint64_t)(1024 + (kk - 4) * 2);
}

// Byte offset of (row, 16B-chunk c8) inside a 128x128-fp16 blocked-atom SW128 tile.
// atom = 8 rows x 128B; atom_offset = atom_row + atom_col*16.
__device__ __forceinline__ uint32_t hx_tile_off16(int row, int c8) {
    uint32_t byte = (uint32_t)c8 * 16u;
    uint32_t atom = (uint32_t)(row >> 3) + ((byte >> 7) << 4);
    uint32_t off = atom * 1024u + (uint32_t)(row & 7) * 128u + (byte & 127u);
    return off ^ ((off >> 3) & 0x70u);
}

// ---------------- SMEM layout (dynamic) -------------------------------------
#define OFF_QHI 1024
#define OFF_QLO (OFF_QHI + 32768)
#define OFF_KHI (OFF_QLO + 32768)
#define OFF_KLO (OFF_KHI + 32768)
#define OFF_KT  (OFF_KLO + 32768)
#define OFF_VT  (OFF_KT + 32768)
#define OFF_P   (OFF_VT + 32768)
#define SMEM_TOTAL (OFF_P + 32768)   // 230400 B <= 232448

#define MB_QK 8
#define MB_PV 16

// TMEM column offsets
#define TM_S  0
#define TM_OK 128
#define TM_OV 256

// Load a 128x128 fp16 tile (row stride `stride` elements) into blocked-atom
// SW128 SMEM. 256 threads, 8 x uint4 each.
__device__ __forceinline__ void hx_load_tile(const __half* __restrict__ g,
                                             size_t stride, char* sdst, int tid) {
    #pragma unroll
    for (int i = 0; i < 8; ++i) {
        int idx = tid + i * 256;           // 0..2047
        int r = idx >> 4;
        int c8 = idx & 15;
        uint4 val = *(const uint4*)(g + (size_t)r * stride + (size_t)c8 * 8);
        *(uint4*)(sdst + hx_tile_off16(r, c8)) = val;
    }
}

// ---------------- prep kernels ----------------------------------------------
__global__ void prep_hilo(const float* __restrict__ q, const float* __restrict__ k) {
    int i = blockIdx.x * blockDim.x + threadIdx.x;
    if (i < NKEYS * D) {
        float x = k[i];
        __half h = __float2half_rn(x);
        g_khi[i] = h;
        g_klo[i] = __float2half_rn(x - __half2float(h));
    }
    if (i < NQ * D) {
        float x = q[i];
        __half h = __float2half_rn(x);
        g_qhi[i] = h;
        g_qlo[i] = __float2half_rn(x - __half2float(h));
    }
}

__global__ void prep_transpose(const float* __restrict__ k, const float* __restrict__ v) {
    __shared__ __half sm[32][33];
    const float* src = blockIdx.z ? v : k;
    __half* dst = blockIdx.z ? g_vthi : g_kthi;
    int n0 = blockIdx.x * 32;
    int d0 = blockIdx.y * 32;
    #pragma unroll
    for (int yy = threadIdx.y; yy < 32; yy += 8)
        sm[yy][threadIdx.x] = __float2half_rn(src[(size_t)(n0 + yy) * D + d0 + threadIdx.x]);
    __syncthreads();
    #pragma unroll
    for (int yy = threadIdx.y; yy < 32; yy += 8)
        dst[(size_t)(d0 + yy) * NKEYS + n0 + threadIdx.x] = sm[threadIdx.x][yy];
}

// ---------------- main flash kernel ------------------------------------------
__global__ __launch_bounds__(256, 1) void flash_main() {
#if HX_HAS_TCGEN05
    extern __shared__ char smem[];
    uint32_t sb = hx_smem_u32(smem);
    int tid = threadIdx.x;
    int wid = tid >> 5;

    int split = blockIdx.x & (NSPLIT - 1);
    int qt    = blockIdx.x >> 2;
    int q0 = qt * 128;
    int n0 = split * KEYS_PER_SPLIT;

    if (wid == 0) HX_TCALLOC(sb, 512); else HX_TCRELINQ();
    if (tid == 0) { HX_MBINIT(sb + MB_QK, 1); HX_MBINIT(sb + MB_PV, 1); }
    __syncthreads();
    uint32_t tmem;
    asm volatile("ld.shared.b32 %0, [%1];" : "=r"(tmem) : "r"(sb));

    // persistent Q tiles
    hx_load_tile(g_qhi + (size_t)q0 * D, D, smem + OFF_QHI, tid);
    hx_load_tile(g_qlo + (size_t)q0 * D, D, smem + OFF_QLO, tid);
    HX_FENCE_ASYNC();
    __syncthreads();

    uint64_t d_qhi = hx_desc(sb + OFF_QHI);
    uint64_t d_qlo = hx_desc(sb + OFF_QLO);
    uint64_t d_khi = hx_desc(sb + OFF_KHI);
    uint64_t d_klo = hx_desc(sb + OFF_KLO);
    uint64_t d_kt  = hx_desc(sb + OFF_KT);
    uint64_t d_vt  = hx_desc(sb + OFF_VT);
    uint64_t d_p   = hx_desc(sb + OFF_P);

    int phq = 0, phv = 0;
    float m = -1e30f;
    float lsum = 0.0f;

    // ---------------- Pass A: approximate row max (hi*hi only) --------------
    for (int t = 0; t < NTILES; ++t) {
        hx_load_tile(g_khi + (size_t)(n0 + t * BN) * D, D, smem + OFF_KHI, tid);
        HX_FENCE_ASYNC();
        __syncthreads();
        if (wid == 0 && hx_elect()) {
            #pragma unroll
            for (int kk = 0; kk < 8; ++kk)
                hx_mma_f16_ss(tmem + TM_S, d_qhi + hx_koff(kk), d_khi + hx_koff(kk),
                              HX_IDESC, kk > 0 ? 1u : 0u);
            HX_COMMIT(sb + MB_QK);
        }
        HX_MBWAIT(sb + MB_QK, phq); phq ^= 1;
        HX_FENCE_AFTER();
        if (tid < 128) {
            #pragma unroll
            for (int c = 0; c < 4; ++c) {
                uint32_t r[32];
                HX_LDTM_X32(r, tmem + TM_S + c * 32);
                HX_WAIT_LD();
                #pragma unroll
                for (int j = 0; j < 32; ++j)
                    m = fmaxf(m, __uint_as_float(r[j]));
            }
            HX_FENCE_BEFORE();
        }
        __syncthreads();
    }

    // ---------------- Pass B: exact logits, exp, PV accumulation ------------
    for (int t = 0; t < NTILES; ++t) {
        int nb = n0 + t * BN;
        hx_load_tile(g_khi + (size_t)nb * D, D, smem + OFF_KHI, tid);
        hx_load_tile(g_klo + (size_t)nb * D, D, smem + OFF_KLO, tid);
        hx_load_tile(g_kthi + nb, NKEYS, smem + OFF_KT, tid);
        hx_load_tile(g_vthi + nb, NKEYS, smem + OFF_VT, tid);
        HX_FENCE_ASYNC();
        __syncthreads();

        if (wid == 0 && hx_elect()) {
            #pragma unroll
            for (int kk = 0; kk < 8; ++kk)
                hx_mma_f16_ss(tmem + TM_S, d_qhi + hx_koff(kk), d_khi + hx_koff(kk),
                              HX_IDESC, kk > 0 ? 1u : 0u);
            #pragma unroll
            for (int kk = 0; kk < 8; ++kk)
                hx_mma_f16_ss(tmem + TM_S, d_qhi + hx_koff(kk), d_klo + hx_koff(kk),
                              HX_IDESC, 1u);
            #pragma unroll
            for (int kk = 0; kk < 8; ++kk)
                hx_mma_f16_ss(tmem + TM_S, d_qlo + hx_koff(kk), d_khi + hx_koff(kk),
                              HX_IDESC, 1u);
            HX_COMMIT(sb + MB_QK);
        }
        HX_MBWAIT(sb + MB_QK, phq); phq ^= 1;
        HX_FENCE_AFTER();

        if (tid < 128) {
            #pragma unroll
            for (int c = 0; c < 4; ++c) {
                uint32_t r[32];
                HX_LDTM_X32(r, tmem + TM_S + c * 32);
                HX_WAIT_LD();
                uint32_t h2[16];
                #pragma unroll
                for (int j = 0; j < 16; ++j) {
                    float p0 = __expf(__uint_as_float(r[2 * j])     - m);
                    float p1 = __expf(__uint_as_float(r[2 * j + 1]) - m);
                    lsum += p0 + p1;
                    __half2 hh = __floats2half2_rn(p0, p1);
                    h2[j] = *(uint32_t*)&hh;
                }
                #pragma unroll
                for (int u = 0; u < 4; ++u) {
                    uint4 val = make_uint4(h2[4*u], h2[4*u+1], h2[4*u+2], h2[4*u+3]);
                    *(uint4*)(smem + OFF_P + hx_tile_off16(tid, c * 4 + u)) = val;
                }
            }
            HX_FENCE_BEFORE();
        }
        HX_FENCE_ASYNC();
        __syncthreads();

        if (wid == 0 && hx_elect()) {
            uint32_t accbase = (t > 0) ? 1u : 0u;
            #pragma unroll
            for (int kk = 0; kk < 8; ++kk)
                hx_mma_f16_ss(tmem + TM_OK, d_p + hx_koff(kk), d_kt + hx_koff(kk),
                              HX_IDESC, (accbase | (kk > 0)) ? 1u : 0u);
            #pragma unroll
            for (int kk = 0; kk < 8; ++kk)
                hx_mma_f16_ss(tmem + TM_OV, d_p + hx_koff(kk), d_vt + hx_koff(kk),
                              HX_IDESC, (accbase | (kk > 0)) ? 1u : 0u);
            HX_COMMIT(sb + MB_PV);
        }
        HX_MBWAIT(sb + MB_PV, phv); phv ^= 1;
    }

    // ---------------- write split partials -----------------------------------
    HX_FENCE_AFTER();
    if (tid < 128) {
        int q = q0 + tid;
        g_m[split * NQ + q] = m;
        g_l[split * NQ + q] = lsum;
        size_t base = ((size_t)split * NQ + q) * D;
        #pragma unroll
        for (int c = 0; c < 4; ++c) {
            uint32_t r[32];
            HX_LDTM_X32(r, tmem + TM_OK + c * 32);
            HX_WAIT_LD();
            #pragma unroll
            for (int j = 0; j < 32; ++j)
                g_ok[base + c * 32 + j] = __uint_as_float(r[j]);
        }
        #pragma unroll
        for (int c = 0; c < 4; ++c) {
            uint32_t r[32];
            HX_LDTM_X32(r, tmem + TM_OV + c * 32);
            HX_WAIT_LD();
            #pragma unroll
            for (int j = 0; j < 32; ++j)
                g_ov[base + c * 32 + j] = __uint_as_float(r[j]);
        }
        HX_FENCE_BEFORE();
    }
    __syncthreads();
    if (wid == 0) HX_TCDEALLOC(tmem, 512);
#endif  // HX_HAS_TCGEN05
}

// ---------------- reduction over splits --------------------------------------
__global__ void reduce_kernel(float* __restrict__ out) {
    int q = blockIdx.x;
    int d = threadIdx.x;
    float m0 = g_m[0 * NQ + q], m1 = g_m[1 * NQ + q];
    float m2 = g_m[2 * NQ + q], m3 = g_m[3 * NQ + q];
    float ms = fmaxf(fmaxf(m0, m1), fmaxf(m2, m3));
    float w0 = __expf(m0 - ms), w1 = __expf(m1 - ms);
    float w2 = __expf(m2 - ms), w3 = __expf(m3 - ms);
    float denom = g_l[0 * NQ + q] * w0 + g_l[1 * NQ + q] * w1 +
                  g_l[2 * NQ + q] * w2 + g_l[3 * NQ + q] * w3;
    float inv = 1.0f / denom;
    size_t i0 = ((size_t)0 * NQ + q) * D + d;
    size_t i1 = ((size_t)1 * NQ + q) * D + d;
    size_t i2 = ((size_t)2 * NQ + q) * D + d;
    size_t i3 = ((size_t)3 * NQ + q) * D + d;
    float ok = g_ok[i0] * w0 + g_ok[i1] * w1 + g_ok[i2] * w2 + g_ok[i3] * w3;
    float ov = g_ov[i0] * w0 + g_ov[i1] * w1 + g_ov[i2] * w2 + g_ov[i3] * w3;
    out[(size_t)q * D + d] = ok * inv;
    out[(size_t)NQ * D + (size_t)q * D + d] = ov * inv;
}

// ---------------- launch ------------------------------------------------------
extern "C" void kernel_launch(void* const* d_in, const int* in_sizes, int n_in,
                              void* d_out, int out_size) {
    const float* q = (const float*)d_in[0];
    const float* k = (const float*)d_in[1];
    const float* v = (const float*)d_in[2];
    float* out = (float*)d_out;
    (void)in_sizes; (void)n_in; (void)out_size;

    cudaFuncSetAttribute(flash_main, cudaFuncAttributeMaxDynamicSharedMemorySize,
                         SMEM_TOTAL);

    prep_hilo<<<(NKEYS * D) / 256, 256>>>(q, k);
    dim3 gt(NKEYS / 32, D / 32, 2), bt(32, 8);
    prep_transpose<<<gt, bt>>>(k, v);
    flash_main<<<NCTA, 256, SMEM_TOTAL>>>();
    reduce_kernel<<<NQ, 128>>>(out);
}

// round 3
// speedup vs baseline: 1.0044x; 1.0044x over previous
#include <cuda_runtime.h>
#include <cuda_fp16.h>
#include <cstdint>

// ============================================================================
// LaminiIndex: full attention over 65536 embeddings.
//   logits = Q(4096x128) K^T ; P = softmax(logits) ; out_k = P K ; out_v = P V
// Strategy: tcgen05 fp16 flash attention, split-precision QK (hi/lo fp16,
// 3 MMAs -> ~fp32-exact logits), fixed-max 2-pass softmax (no TMEM rescale),
// split-KV x4 + reduction kernel.
// tcgen05 is arch-ACCELERATED: only legal under sm_103a/sm_100a targets, so
// the device body is guarded by the family feature macros; the plain
// compute_103 PTX pass compiles a stub (never selected at runtime on GB300).
// ============================================================================

#if defined(__CUDA_ARCH_FEAT_SM103_ALL) || defined(__CUDA_ARCH_FEAT_SM100_ALL)
#define HX_HAS_TCGEN05 1
#else
#define HX_HAS_TCGEN05 0
#endif

#define D        128
#define NQ       4096
#define NKEYS    65536
#define NSPLIT   4
#define KEYS_PER_SPLIT (NKEYS / NSPLIT)   // 16384
#define BN       128
#define NTILES   (KEYS_PER_SPLIT / BN)    // 128
#define NQTILES  (NQ / 128)               // 32
#define NCTA     (NSPLIT * NQTILES)       // 128

// ---------------- device scratch (allowed: __device__ globals) -------------
__device__ __half g_qhi[NQ * D];
__device__ __half g_qlo[NQ * D];
__device__ __half g_khi[(size_t)NKEYS * D];
__device__ __half g_klo[(size_t)NKEYS * D];
__device__ __half g_kthi[(size_t)D * NKEYS];   // transposed keys  [d][n]
__device__ __half g_vthi[(size_t)D * NKEYS];   // transposed values [d][n]
__device__ float  g_ok[(size_t)NSPLIT * NQ * D];
__device__ float  g_ov[(size_t)NSPLIT * NQ * D];
__device__ float  g_m[NSPLIT * NQ];
__device__ float  g_l[NSPLIT * NQ];

// ---------------- PTX helpers ----------------------------------------------
__device__ __forceinline__ uint32_t hx_smem_u32(const void* p) {
    uint32_t a;
    asm("{ .reg .u64 t; cvta.to.shared.u64 t, %1; cvt.u32.u64 %0, t; }"
        : "=r"(a) : "l"(p));
    return a;
}
__device__ __forceinline__ uint32_t hx_elect() {
    uint32_t p;
    asm volatile("{\n\t.reg .pred p;\n\telect.sync _|p, 0xFFFFFFFF;\n\t"
                 "selp.b32 %0, 1, 0, p;\n\t}" : "=r"(p));
    return p;
}
#define HX_TCALLOC(sa, n) \
    asm volatile("tcgen05.alloc.cta_group::1.sync.aligned.shared::cta.b32 [%0], %1;" \
                 :: "r"((uint32_t)(sa)), "r"((uint32_t)(n)) : "memory")
#define HX_TCDEALLOC(t, n) \
    asm volatile("tcgen05.dealloc.cta_group::1.sync.aligned.b32 %0, %1;" :: "r"(t), "r"(n))
#define HX_TCRELINQ() \
    asm volatile("tcgen05.relinquish_alloc_permit.cta_group::1.sync.aligned;")
#define HX_COMMIT(mb) \
    asm volatile("tcgen05.commit.cta_group::1.mbarrier::arrive::one.shared::cluster.b64 [%0];" \
                 :: "r"((uint32_t)(mb)) : "memory")
#define HX_FENCE_BEFORE() asm volatile("tcgen05.fence::before_thread_sync;" ::: "memory")
#define HX_FENCE_AFTER()  asm volatile("tcgen05.fence::after_thread_sync;" ::: "memory")
#define HX_WAIT_LD()      asm volatile("tcgen05.wait::ld.sync.aligned;" ::: "memory")
#define HX_FENCE_ASYNC()  asm volatile("fence.proxy.async.shared::cta;" ::: "memory")
#define HX_MBINIT(mb, c) \
    asm volatile("mbarrier.init.shared.b64 [%0], %1;" \
                 :: "r"((uint32_t)(mb)), "r"((uint32_t)(c)) : "memory")

#define HX_MBWAIT(mbaddr, ph) do {                                            \
    uint32_t _mb = (uint32_t)(mbaddr);                                        \
    uint32_t _pa = (uint32_t)(ph);                                            \
    uint32_t _done;                                                           \
    asm volatile("{\n\t.reg .pred p;\n\t"                                     \
        "mbarrier.try_wait.parity.acquire.cta.shared::cta.b64 p, [%1], %2;\n\t" \
        "selp.b32 %0, 1, 0, p;\n\t}"                                          \
        : "=r"(_done) : "r"(_mb), "r"(_pa) : "memory");                       \
    if (!_done) {                                                             \
        asm volatile("{\n\t.reg .pred P1;\n\t"                                \
            "WL_%=:\n\t"                                                      \
            "mbarrier.try_wait.parity.acquire.cta.shared::cta.b64 P1, [%0], %1, 0x989680;\n\t" \
            "@P1 bra.uni WD_%=;\n\t"                                          \
            "bra.uni WL_%=;\n\t"                                              \
            "WD_%=:\n\t}" :: "r"(_mb), "r"(_pa) : "memory");                  \
    }                                                                         \
} while (0)

#define HX_LDTM_X32(r, addr) \
    asm volatile("tcgen05.ld.sync.aligned.32x32b.x32.b32 "                    \
        "{%0, %1, %2, %3, %4, %5, %6, %7, %8, %9, %10, %11, %12, %13, %14, %15, " \
        " %16, %17, %18, %19, %20, %21, %22, %23, %24, %25, %26, %27, %28, %29, %30, %31}, [%32];" \
        : "=r"((r)[0]),  "=r"((r)[1]),  "=r"((r)[2]),  "=r"((r)[3]),          \
          "=r"((r)[4]),  "=r"((r)[5]),  "=r"((r)[6]),  "=r"((r)[7]),          \
          "=r"((r)[8]),  "=r"((r)[9]),  "=r"((r)[10]), "=r"((r)[11]),         \
          "=r"((r)[12]), "=r"((r)[13]), "=r"((r)[14]), "=r"((r)[15]),         \
          "=r"((r)[16]), "=r"((r)[17]), "=r"((r)[18]), "=r"((r)[19]),         \
          "=r"((r)[20]), "=r"((r)[21]), "=r"((r)[22]), "=r"((r)[23]),         \
          "=r"((r)[24]), "=r"((r)[25]), "=r"((r)[26]), "=r"((r)[27]),         \
          "=r"((r)[28]), "=r"((r)[29]), "=r"((r)[30]), "=r"((r)[31])          \
        : "r"(addr))

__device__ __forceinline__ void hx_mma_f16_ss(uint32_t d, uint64_t a, uint64_t b,
                                              uint32_t idesc, uint32_t acc) {
#if HX_HAS_TCGEN05
    asm volatile("{\n\t.reg .pred p;\n\tsetp.ne.u32 p, %5, 0;\n\t"
        "tcgen05.mma.cta_group::1.kind::f16 [%0], %1, %2, %3, {%4, %4, %4, %4}, p;\n\t}"
        :: "r"(d), "l"(a), "l"(b), "r"(idesc), "r"(0u), "r"(acc) : "memory");
#endif
}

// SW128 K-major SMEM descriptor (LBO=1, SBO=64, version=1) — test_mma_iter layout.
__device__ __forceinline__ uint64_t hx_desc(uint32_t saddr) {
    return ((uint64_t)2 << 61) | ((uint64_t)1 << 46) | ((uint64_t)64 << 32) |
           ((uint64_t)1 << 16) | ((uint64_t)(saddr >> 4) & 0x3FFF);
}

// idesc kind::f16: dtype=F32(1<<4), atype=btype=F16(0), N=128 (16<<17), M=128 (8<<24)
#define HX_IDESC 0x08200010u

// K-step descriptor offset (16 fp16 = 32B per step; 128-row tile => 16 atom rows,
// atom-col 1 starts at 16*1024 B = 1024 units of 16B).
__device__ __forceinline__ uint64_t hx_koff(int kk) {
    return (kk < 4) ? (uint64_t)(kk * 2) : (uint64_t)(1024 + (kk - 4) * 2);
}

// Byte offset of (row, 16B-chunk c8) inside a 128x128-fp16 blocked-atom SW128 tile.
// atom = 8 rows x 128B; atom_offset = atom_row + atom_col*16.
__device__ __forceinline__ uint32_t hx_tile_off16(int row, int c8) {
    uint32_t byte = (uint32_t)c8 * 16u;
    uint32_t atom = (uint32_t)(row >> 3) + ((byte >> 7) << 4);
    uint32_t off = atom * 1024u + (uint32_t)(row & 7) * 128u + (byte & 127u);
    return off ^ ((off >> 3) & 0x70u);
}

// ---------------- SMEM layout (dynamic) -------------------------------------
#define OFF_QHI 1024
#define OFF_QLO (OFF_QHI + 32768)
#define OFF_KHI (OFF_QLO + 32768)
#define OFF_KLO (OFF_KHI + 32768)
#define OFF_KT  (OFF_KLO + 32768)
#define OFF_VT  (OFF_KT + 32768)
#define OFF_P   (OFF_VT + 32768)
#define SMEM_TOTAL (OFF_P + 32768)   // 230400 B <= 232448

#define MB_QK 8
#define MB_PV 16

// TMEM column offsets
#define TM_S  0
#define TM_OK 128
#define TM_OV 256

// Load a 128x128 fp16 tile (row stride `stride` elements) into blocked-atom
// SW128 SMEM. 256 threads, 8 x uint4 each.
__device__ __forceinline__ void hx_load_tile(const __half* __restrict__ g,
                                             size_t stride, char* sdst, int tid) {
    #pragma unroll
    for (int i = 0; i < 8; ++i) {
        int idx = tid + i * 256;           // 0..2047
        int r = idx >> 4;
        int c8 = idx & 15;
        uint4 val = *(const uint4*)(g + (size_t)r * stride + (size_t)c8 * 8);
        *(uint4*)(sdst + hx_tile_off16(r, c8)) = val;
    }
}

// ---------------- prep kernels ----------------------------------------------
__global__ void prep_hilo(const float* __restrict__ q, const float* __restrict__ k) {
    int i = blockIdx.x * blockDim.x + threadIdx.x;
    if (i < NKEYS * D) {
        float x = k[i];
        __half h = __float2half_rn(x);
        g_khi[i] = h;
        g_klo[i] = __float2half_rn(x - __half2float(h));
    }
    if (i < NQ * D) {
        float x = q[i];
        __half h = __float2half_rn(x);
        g_qhi[i] = h;
        g_qlo[i] = __float2half_rn(x - __half2float(h));
    }
}

__global__ void prep_transpose(const float* __restrict__ k, const float* __restrict__ v) {
    __shared__ __half sm[32][33];
    const float* src = blockIdx.z ? v : k;
    __half* dst = blockIdx.z ? g_vthi : g_kthi;
    int n0 = blockIdx.x * 32;
    int d0 = blockIdx.y * 32;
    #pragma unroll
    for (int yy = threadIdx.y; yy < 32; yy += 8)
        sm[yy][threadIdx.x] = __float2half_rn(src[(size_t)(n0 + yy) * D + d0 + threadIdx.x]);
    __syncthreads();
    #pragma unroll
    for (int yy = threadIdx.y; yy < 32; yy += 8)
        dst[(size_t)(d0 + yy) * NKEYS + n0 + threadIdx.x] = sm[threadIdx.x][yy];
}

// ---------------- main flash kernel ------------------------------------------
__global__ __launch_bounds__(256, 1) void flash_main() {
#if HX_HAS_TCGEN05
    extern __shared__ char smem[];
    uint32_t sb = hx_smem_u32(smem);
    int tid = threadIdx.x;
    int wid = tid >> 5;

    int split = blockIdx.x & (NSPLIT - 1);
    int qt    = blockIdx.x >> 2;
    int q0 = qt * 128;
    int n0 = split * KEYS_PER_SPLIT;

    if (wid == 0) HX_TCALLOC(sb, 512); else HX_TCRELINQ();
    if (tid == 0) { HX_MBINIT(sb + MB_QK, 1); HX_MBINIT(sb + MB_PV, 1); }
    __syncthreads();
    uint32_t tmem;
    asm volatile("ld.shared.b32 %0, [%1];" : "=r"(tmem) : "r"(sb));

    // persistent Q tiles
    hx_load_tile(g_qhi + (size_t)q0 * D, D, smem + OFF_QHI, tid);
    hx_load_tile(g_qlo + (size_t)q0 * D, D, smem + OFF_QLO, tid);
    HX_FENCE_ASYNC();
    __syncthreads();

    uint64_t d_qhi = hx_desc(sb + OFF_QHI);
    uint64_t d_qlo = hx_desc(sb + OFF_QLO);
    uint64_t d_khi = hx_desc(sb + OFF_KHI);
    uint64_t d_klo = hx_desc(sb + OFF_KLO);
    uint64_t d_kt  = hx_desc(sb + OFF_KT);
    uint64_t d_vt  = hx_desc(sb + OFF_VT);
    uint64_t d_p   = hx_desc(sb + OFF_P);

    int phq = 0, phv = 0;
    float m = -1e30f;
    float lsum = 0.0f;

    // ---------------- Pass A: approximate row max (hi*hi only) --------------
    for (int t = 0; t < NTILES; ++t) {
        hx_load_tile(g_khi + (size_t)(n0 + t * BN) * D, D, smem + OFF_KHI, tid);
        HX_FENCE_ASYNC();
        __syncthreads();
        if (wid == 0 && hx_elect()) {
            #pragma unroll
            for (int kk = 0; kk < 8; ++kk)
                hx_mma_f16_ss(tmem + TM_S, d_qhi + hx_koff(kk), d_khi + hx_koff(kk),
                              HX_IDESC, kk > 0 ? 1u : 0u);
            HX_COMMIT(sb + MB_QK);
        }
        HX_MBWAIT(sb + MB_QK, phq); phq ^= 1;
        HX_FENCE_AFTER();
        if (tid < 128) {
            #pragma unroll
            for (int c = 0; c < 4; ++c) {
                uint32_t r[32];
                HX_LDTM_X32(r, tmem + TM_S + c * 32);
                HX_WAIT_LD();
                #pragma unroll
                for (int j = 0; j < 32; ++j)
                    m = fmaxf(m, __uint_as_float(r[j]));
            }
            HX_FENCE_BEFORE();
        }
        __syncthreads();
    }

    // ---------------- Pass B: exact logits, exp, PV accumulation ------------
    for (int t = 0; t < NTILES; ++t) {
        int nb = n0 + t * BN;
        hx_load_tile(g_khi + (size_t)nb * D, D, smem + OFF_KHI, tid);
        hx_load_tile(g_klo + (size_t)nb * D, D, smem + OFF_KLO, tid);
        hx_load_tile(g_kthi + nb, NKEYS, smem + OFF_KT, tid);
        hx_load_tile(g_vthi + nb, NKEYS, smem + OFF_VT, tid);
        HX_FENCE_ASYNC();
        __syncthreads();

        if (wid == 0 && hx_elect()) {
            #pragma unroll
            for (int kk = 0; kk < 8; ++kk)
                hx_mma_f16_ss(tmem + TM_S, d_qhi + hx_koff(kk), d_khi + hx_koff(kk),
                              HX_IDESC, kk > 0 ? 1u : 0u);
            #pragma unroll
            for (int kk = 0; kk < 8; ++kk)
                hx_mma_f16_ss(tmem + TM_S, d_qhi + hx_koff(kk), d_klo + hx_koff(kk),
                              HX_IDESC, 1u);
            #pragma unroll
            for (int kk = 0; kk < 8; ++kk)
                hx_mma_f16_ss(tmem + TM_S, d_qlo + hx_koff(kk), d_khi + hx_koff(kk),
                              HX_IDESC, 1u);
            HX_COMMIT(sb + MB_QK);
        }
        HX_MBWAIT(sb + MB_QK, phq); phq ^= 1;
        HX_FENCE_AFTER();

        if (tid < 128) {
            #pragma unroll
            for (int c = 0; c < 4; ++c) {
                uint32_t r[32];
                HX_LDTM_X32(r, tmem + TM_S + c * 32);
                HX_WAIT_LD();
                uint32_t h2[16];
                #pragma unroll
                for (int j = 0; j < 16; ++j) {
                    float p0 = __expf(__uint_as_float(r[2 * j])     - m);
                    float p1 = __expf(__uint_as_float(r[2 * j + 1]) - m);
                    lsum += p0 + p1;
                    __half2 hh = __floats2half2_rn(p0, p1);
                    h2[j] = *(uint32_t*)&hh;
                }
                #pragma unroll
                for (int u = 0; u < 4; ++u) {
                    uint4 val = make_uint4(h2[4*u], h2[4*u+1], h2[4*u+2], h2[4*u+3]);
                    *(uint4*)(smem + OFF_P + hx_tile_off16(tid, c * 4 + u)) = val;
                }
            }
            HX_FENCE_BEFORE();
        }
        HX_FENCE_ASYNC();
        __syncthreads();

        if (wid == 0 && hx_elect()) {
            uint32_t accbase = (t > 0) ? 1u : 0u;
            #pragma unroll
            for (int kk = 0; kk < 8; ++kk)
                hx_mma_f16_ss(tmem + TM_OK, d_p + hx_koff(kk), d_kt + hx_koff(kk),
                              HX_IDESC, (accbase | (kk > 0)) ? 1u : 0u);
            #pragma unroll
            for (int kk = 0; kk < 8; ++kk)
                hx_mma_f16_ss(tmem + TM_OV, d_p + hx_koff(kk), d_vt + hx_koff(kk),
                              HX_IDESC, (accbase | (kk > 0)) ? 1u : 0u);
            HX_COMMIT(sb + MB_PV);
        }
        HX_MBWAIT(sb + MB_PV, phv); phv ^= 1;
    }

    // ---------------- write split partials -----------------------------------
    HX_FENCE_AFTER();
    if (tid < 128) {
        int q = q0 + tid;
        g_m[split * NQ + q] = m;
        g_l[split * NQ + q] = lsum;
        size_t base = ((size_t)split * NQ + q) * D;
        #pragma unroll
        for (int c = 0; c < 4; ++c) {
            uint32_t r[32];
            HX_LDTM_X32(r, tmem + TM_OK + c * 32);
            HX_WAIT_LD();
            #pragma unroll
            for (int j = 0; j < 32; ++j)
                g_ok[base + c * 32 + j] = __uint_as_float(r[j]);
        }
        #pragma unroll
        for (int c = 0; c < 4; ++c) {
            uint32_t r[32];
            HX_LDTM_X32(r, tmem + TM_OV + c * 32);
            HX_WAIT_LD();
            #pragma unroll
            for (int j = 0; j < 32; ++j)
                g_ov[base + c * 32 + j] = __uint_as_float(r[j]);
        }
        HX_FENCE_BEFORE();
    }
    __syncthreads();
    if (wid == 0) HX_TCDEALLOC(tmem, 512);
#endif  // HX_HAS_TCGEN05
}

// ---------------- reduction over splits --------------------------------------
__global__ void reduce_kernel(float* __restrict__ out) {
    int q = blockIdx.x;
    int d = threadIdx.x;
    float m0 = g_m[0 * NQ + q], m1 = g_m[1 * NQ + q];
    float m2 = g_m[2 * NQ + q], m3 = g_m[3 * NQ + q];
    float ms = fmaxf(fmaxf(m0, m1), fmaxf(m2, m3));
    float w0 = __expf(m0 - ms), w1 = __expf(m1 - ms);
    float w2 = __expf(m2 - ms), w3 = __expf(m3 - ms);
    float denom = g_l[0 * NQ + q] * w0 + g_l[1 * NQ + q] * w1 +
                  g_l[2 * NQ + q] * w2 + g_l[3 * NQ + q] * w3;
    float inv = 1.0f / denom;
    size_t i0 = ((size_t)0 * NQ + q) * D + d;
    size_t i1 = ((size_t)1 * NQ + q) * D + d;
    size_t i2 = ((size_t)2 * NQ + q) * D + d;
    size_t i3 = ((size_t)3 * NQ + q) * D + d;
    float ok = g_ok[i0] * w0 + g_ok[i1] * w1 + g_ok[i2] * w2 + g_ok[i3] * w3;
    float ov = g_ov[i0] * w0 + g_ov[i1] * w1 + g_ov[i2] * w2 + g_ov[i3] * w3;
    out[(size_t)q * D + d] = ok * inv;
    out[(size_t)NQ * D + (size_t)q * D + d] = ov * inv;
}

// ---------------- launch ------------------------------------------------------
extern "C" void kernel_launch(void* const* d_in, const int* in_sizes, int n_in,
                              void* d_out, int out_size) {
    const float* q = (const float*)d_in[0];
    const float* k = (const float*)d_in[1];
    const float* v = (const float*)d_in[2];
    float* out = (float*)d_out;
    (void)in_sizes; (void)n_in; (void)out_size;

    cudaFuncSetAttribute(flash_main, cudaFuncAttributeMaxDynamicSharedMemorySize,
                         SMEM_TOTAL);

    prep_hilo<<<(NKEYS * D) / 256, 256>>>(q, k);
    dim3 gt(NKEYS / 32, D / 32, 2), bt(32, 8);
    prep_transpose<<<gt, bt>>>(k, v);
    flash_main<<<NCTA, 256, SMEM_TOTAL>>>();
    reduce_kernel<<<NQ, 128>>>(out);
}